// round 14
// baseline (speedup 1.0000x reference)
#include <cuda_runtime.h>
#include <cuda_bf16.h>
#include <cuda_fp16.h>
#include <math.h>
#include <stdint.h>

#define BB   32
#define NN   512
#define INF  1024
#define OUTF 4096
#define HID  128
#define R2   128           // Woodbury dimension = 2*K_ROT*RANK
#define TOK  (BB*NN)       // 16384
#define CTRL (3*INF)       // 3072
#define KTOT 1152          // INF + R2

#define MT 128
#define NT 128
#define KT 32

// ---------------- device scratch (no allocations allowed) ----------------
__device__ float g_z[BB*CTRL];
__device__ float g_svec[BB*R2];
__device__ float g_rotgate[BB];
__device__ float g_scalegate[BB];
__device__ float g_scoeff[BB*8];
__device__ float g_P[INF*R2];          // [d][i]
__device__ float g_Q[INF*R2];          // [d][i]
__device__ float g_G0[R2*R2];          // Q0^T P
__device__ float g_K[BB*R2*R2];        // per-batch g * Minv * S
__device__ float g_Gtp[8*OUTF*R2];     // split-K partials for G
__device__ float g_Y[(size_t)TOK*R2];  // x @ P
__device__ float g_scale[BB*OUTF];

// fp16 operands: A = [x | U], B = [W | Gt], Pt = P^T (for Y HMMA)
__device__ __align__(256) __half g_Ah[(size_t)TOK*KTOT];
__device__ __align__(256) __half g_Bh[(size_t)OUTF*KTOT];
__device__ __align__(256) __half g_Pth[(size_t)R2*INF];   // [i][d]

// =====================  PTX helpers (plain compute_103-safe)  =====================
__device__ __forceinline__ uint32_t smem_u32(const void* p) {
    uint32_t a;
    asm("{ .reg .u64 t; cvta.to.shared.u64 t, %1; cvt.u32.u64 %0, t; }" : "=r"(a) : "l"(p));
    return a;
}
#define CP_ASYNC16(sa, gp) asm volatile("cp.async.cg.shared.global [%0], [%1], 16;" :: "r"(sa), "l"(gp) : "memory")
#define CP_COMMIT()        asm volatile("cp.async.commit_group;" ::: "memory")
#define CP_WAIT(n)         asm volatile("cp.async.wait_group %0;" :: "n"(n) : "memory")

__device__ __forceinline__ void ldsm_x4(uint32_t* r, uint32_t addr) {
    asm volatile("ldmatrix.sync.aligned.m8n8.x4.shared.b16 {%0,%1,%2,%3}, [%4];"
        : "=r"(r[0]), "=r"(r[1]), "=r"(r[2]), "=r"(r[3]) : "r"(addr));
}
__device__ __forceinline__ void mma16816h(float* c, const uint32_t* a, const uint32_t* b) {
    asm volatile("mma.sync.aligned.m16n8k16.row.col.f32.f16.f16.f32 "
        "{%0,%1,%2,%3}, {%4,%5,%6,%7}, {%8,%9}, {%0,%1,%2,%3};"
        : "+f"(c[0]), "+f"(c[1]), "+f"(c[2]), "+f"(c[3])
        : "r"(a[0]), "r"(a[1]), "r"(a[2]), "r"(a[3]), "r"(b[0]), "r"(b[1]));
}

// ---------------- 1. fused prep: pack (blocks 0..511) + stats (blocks 512..639) ----------------
__global__ void prep_kernel(const float* __restrict__ x,
                            const float* __restrict__ lb, const float* __restrict__ rb) {
    int bid = blockIdx.x;
    if (bid < 512) {
        // pack P, Q0 (+ fp16 P^T)
        int idx = bid * 256 + threadIdx.x;     // 0..131071 = INF*R2
        int d = idx >> 7;
        int i = idx & 127;
        int hi = i >> 6;
        int k = (i & 63) >> 3;
        int r = i & 7;
        size_t off = ((size_t)k * INF + d) * 8 + r;
        float L = lb[off], R = rb[off];
        float pv = hi ? R : L;
        g_P[d*R2 + i] = pv;
        g_Q[d*R2 + i] = hi ? -L : R;
        g_Pth[(size_t)i * INF + d] = __float2half_rn(pv);
    } else {
        // stats: z = [cls, mean, var]
        int ib = bid - 512;                    // 0..127
        int b = ib >> 2;
        int f = (ib & 3) * 256 + threadIdx.x;
        const float* xp = x + (size_t)b * NN * INF + f;
        float cls = xp[0];
        float s = 0.f, s2 = 0.f;
#pragma unroll 8
        for (int n = 0; n < NN; n++) {
            float v = xp[(size_t)n * INF];
            s += v; s2 += v * v;
        }
        float mean = s * (1.0f / NN);
        float var  = s2 * (1.0f / NN) - mean * mean;
        g_z[b*CTRL + f]         = cls;
        g_z[b*CTRL + INF + f]   = mean;
        g_z[b*CTRL + 2*INF + f] = var;
    }
}

// ---------------- 3. G0 = Q0^T P (128x128, K=1024) ----------------
__global__ void g0_kernel() {
    int i = blockIdx.x;
    int j = threadIdx.x;
    float acc = 0.f;
#pragma unroll 8
    for (int d = 0; d < INF; d++)
        acc += g_Q[d*R2 + i] * g_P[d*R2 + j];
    g_G0[i*R2 + j] = acc;
}

// ---------------- 5. controller MLP + norms (inline) + coeffs + gates + svec ----------------
__global__ void ctrl_kernel(const float* __restrict__ w1, const float* __restrict__ b1,
                            const float* __restrict__ rcw, const float* __restrict__ rcb,
                            const float* __restrict__ rgw, const float* __restrict__ rgb,
                            const float* __restrict__ scw, const float* __restrict__ scb,
                            const float* __restrict__ sgw, const float* __restrict__ sgb) {
    __shared__ float zsh[CTRL];
    __shared__ float hsh[HID];
    __shared__ float rcsh[8];
    __shared__ float nsh[8];
    int b = blockIdx.x, t = threadIdx.x;
    for (int j = t; j < CTRL; j += HID) zsh[j] = g_z[b*CTRL + j];
    // inline Frobenius norms from Gram blocks of G0
    if (t < 8) {
        int k = t;
        float t1 = 0.f, t2 = 0.f;
        for (int r = 0; r < 8; r++)
            for (int s = 0; s < 8; s++) {
                float LtL = -g_G0[(64 + 8*k + r)*R2 + 8*k + s];
                float RtR =  g_G0[(8*k + r)*R2 + 64 + 8*k + s];
                float RtL_rs = g_G0[(8*k + r)*R2 + 8*k + s];
                float RtL_sr = g_G0[(8*k + s)*R2 + 8*k + r];
                t1 += LtL * RtR;
                t2 += RtL_rs * RtL_sr;
            }
        float n2 = 2.f * (t1 - t2);
        nsh[k] = fmaxf(sqrtf(fmaxf(n2, 0.f)), 1e-6f);
    }
    __syncthreads();
    float acc = b1[t];
    const float* wr = w1 + (size_t)t * CTRL;
    for (int j = 0; j < CTRL; j++) acc += zsh[j] * wr[j];
    float u = 0.7978845608028654f * (acc + 0.044715f * acc * acc * acc);
    hsh[t] = 0.5f * acc * (1.f + tanhf(u));
    __syncthreads();
    if (t < 8) {
        float a = rcb[t];
        const float* w = rcw + t * HID;
        for (int j = 0; j < HID; j++) a += hsh[j] * w[j];
        rcsh[t] = a;
    } else if (t < 16) {
        int k = t - 8;
        float a = scb[k];
        const float* w = scw + k * HID;
        for (int j = 0; j < HID; j++) a += hsh[j] * w[j];
        g_scoeff[b*8 + k] = a;
    } else if (t == 16) {
        float a = rgb[0];
        for (int j = 0; j < HID; j++) a += hsh[j] * rgw[j];
        a += -4.0f;
        g_rotgate[b] = 1.f / (1.f + expf(-a));
    } else if (t == 17) {
        float a = sgb[0];
        for (int j = 0; j < HID; j++) a += hsh[j] * sgw[j];
        a += -2.5f;
        g_scalegate[b] = 1.f / (1.f + expf(-a));
    }
    __syncthreads();
    int k = (t & 63) >> 3;
    g_svec[b*R2 + t] = rcsh[k] / nsh[k];
}

// ---------------- 6. per-batch Gauss-Jordan inverse, K = g*Minv*S ----------------
__global__ void __launch_bounds__(1024) minv_kernel() {
    extern __shared__ float Ms[];
    __shared__ float colv[R2];
    __shared__ float ssh[R2];
    int b = blockIdx.x;
    int tid = threadIdx.x;
    int tcol = tid & 127;
    int grp = tid >> 7;
    if (tid < R2) ssh[tid] = g_svec[b*R2 + tid];
    __syncthreads();
#pragma unroll
    for (int r = 0; r < 16; r++) {
        int i = grp * 16 + r;
        float v = -0.5f * ssh[i] * g_G0[i*R2 + tcol];
        if (i == tcol) v += 1.f;
        Ms[i*R2 + tcol] = v;
    }
    for (int k = 0; k < R2; k++) {
        __syncthreads();
        float invp = 1.f / Ms[k*R2 + k];
        if (tid < R2) colv[tid] = Ms[tid*R2 + k];
        __syncthreads();
        if (grp == 0) {
            float rv = (tcol == k ? 1.f : Ms[k*R2 + tcol]) * invp;
            Ms[k*R2 + tcol] = rv;
        }
        __syncthreads();
        float rk = Ms[k*R2 + tcol];
#pragma unroll
        for (int r = 0; r < 16; r++) {
            int i = grp * 16 + r;
            if (i == k) continue;
            float v = (tcol == k) ? 0.f : Ms[i*R2 + tcol];
            Ms[i*R2 + tcol] = v - colv[i] * rk;
        }
    }
    __syncthreads();
    float g = g_rotgate[b];
#pragma unroll
    for (int r = 0; r < 16; r++) {
        int i = grp * 16 + r;
        g_K[(size_t)b*R2*R2 + i*R2 + tcol] = g * Ms[i*R2 + tcol] * ssh[tcol];
    }
}

// ---------------- 7. G partials (split-K) ----------------
__global__ void __launch_bounds__(256) gtp_kernel(const float* __restrict__ W) {
    __shared__ float As[KT][MT + 4];
    __shared__ float Bs[KT][NT + 4];
    int h0 = blockIdx.x * MT;
    int s = blockIdx.y;
    int d0 = s * 128;
    int tid = threadIdx.x, tx = tid & 15, ty = tid >> 4;
    float acc[8][8];
#pragma unroll
    for (int i = 0; i < 8; i++)
#pragma unroll
        for (int j = 0; j < 8; j++) acc[i][j] = 0.f;
    int lrow = tid >> 1, lcol = (tid & 1) * 16;
    int brow = tid >> 3, bcol = (tid & 7) * 16;
    for (int k0 = 0; k0 < 128; k0 += KT) {
        const float4* ap = (const float4*)(W + (size_t)(h0 + lrow) * INF + d0 + k0 + lcol);
        float4 a0 = ap[0], a1 = ap[1], a2 = ap[2], a3 = ap[3];
        const float4* bp = (const float4*)(g_Q + (size_t)(d0 + k0 + brow) * R2 + bcol);
        float4 b0 = bp[0], b1 = bp[1], b2 = bp[2], b3 = bp[3];
        __syncthreads();
        As[lcol+ 0][lrow]=a0.x; As[lcol+ 1][lrow]=a0.y; As[lcol+ 2][lrow]=a0.z; As[lcol+ 3][lrow]=a0.w;
        As[lcol+ 4][lrow]=a1.x; As[lcol+ 5][lrow]=a1.y; As[lcol+ 6][lrow]=a1.z; As[lcol+ 7][lrow]=a1.w;
        As[lcol+ 8][lrow]=a2.x; As[lcol+ 9][lrow]=a2.y; As[lcol+10][lrow]=a2.z; As[lcol+11][lrow]=a2.w;
        As[lcol+12][lrow]=a3.x; As[lcol+13][lrow]=a3.y; As[lcol+14][lrow]=a3.z; As[lcol+15][lrow]=a3.w;
        *(float4*)&Bs[brow][bcol+ 0] = b0;
        *(float4*)&Bs[brow][bcol+ 4] = b1;
        *(float4*)&Bs[brow][bcol+ 8] = b2;
        *(float4*)&Bs[brow][bcol+12] = b3;
        __syncthreads();
#pragma unroll 8
        for (int kk = 0; kk < KT; kk++) {
            float4 av0 = *(const float4*)&As[kk][ty*8];
            float4 av1 = *(const float4*)&As[kk][ty*8+4];
            float4 bv0 = *(const float4*)&Bs[kk][tx*8];
            float4 bv1 = *(const float4*)&Bs[kk][tx*8+4];
            float av[8] = {av0.x,av0.y,av0.z,av0.w,av1.x,av1.y,av1.z,av1.w};
            float bv[8] = {bv0.x,bv0.y,bv0.z,bv0.w,bv1.x,bv1.y,bv1.z,bv1.w};
#pragma unroll
            for (int i = 0; i < 8; i++)
#pragma unroll
                for (int j = 0; j < 8; j++) acc[i][j] += av[i] * bv[j];
        }
    }
#pragma unroll
    for (int i = 0; i < 8; i++)
#pragma unroll
        for (int j = 0; j < 8; j++)
            g_Gtp[((size_t)s * OUTF + h0 + ty*8 + i) * R2 + tx*8 + j] = acc[i][j];
}

// ---------------- 8. Y = x @ P via fp16 HMMA ----------------
#define YBK     32
#define YNCHUNK (INF / YBK)   // 32
#define YNSTG   3
#define YLDSB   80
#define YSUB    (128 * YLDSB)       // 10240
#define YSTGB   (2 * YSUB)          // 20480

__global__ void __launch_bounds__(256, 1) y_hmma_kernel() {
    extern __shared__ char smemraw[];
    uint32_t sbase = smem_u32(smemraw);
    int tid = threadIdx.x;
    int wid = tid >> 5, lane = tid & 31;
    int t0 = blockIdx.y * 128;
    int warpM = wid >> 2;        // 0..1 (64 rows)
    int warpN = wid & 3;         // 0..3 (32 cols)

    const char* gA = (const char*)g_Ah + (size_t)t0 * (KTOT * 2);
    const char* gB = (const char*)g_Pth;

    float acc[4][4][4];
#pragma unroll
    for (int m = 0; m < 4; m++)
#pragma unroll
        for (int n = 0; n < 4; n++)
#pragma unroll
            for (int r = 0; r < 4; r++) acc[m][n][r] = 0.f;

    int arow[2], acol[2];
#pragma unroll
    for (int j = 0; j < 2; j++) { int c = j*256 + tid; arow[j] = c >> 2; acol[j] = (c & 3) * 16; }

#pragma unroll
    for (int pre = 0; pre < YNSTG - 1; pre++) {
        uint32_t st = sbase + pre * YSTGB;
        size_t kb = (size_t)pre * (YBK * 2);
#pragma unroll
        for (int j = 0; j < 2; j++) {
            CP_ASYNC16(st + (uint32_t)arow[j] * YLDSB + acol[j],          gA + (size_t)arow[j] * (KTOT*2) + kb + acol[j]);
            CP_ASYNC16(st + YSUB + (uint32_t)arow[j] * YLDSB + acol[j],   gB + (size_t)arow[j] * (INF*2)  + kb + acol[j]);
        }
        CP_COMMIT();
    }

    for (int it = 0; it < YNCHUNK; it++) {
        if (it < YNCHUNK - 1) { CP_WAIT(1); } else { CP_WAIT(0); }
        __syncthreads();

        if (it + YNSTG - 1 < YNCHUNK) {
            int nxt = it + YNSTG - 1;
            uint32_t st = sbase + (nxt % YNSTG) * YSTGB;
            size_t kb = (size_t)nxt * (YBK * 2);
#pragma unroll
            for (int j = 0; j < 2; j++) {
                CP_ASYNC16(st + (uint32_t)arow[j] * YLDSB + acol[j],        gA + (size_t)arow[j] * (KTOT*2) + kb + acol[j]);
                CP_ASYNC16(st + YSUB + (uint32_t)arow[j] * YLDSB + acol[j], gB + (size_t)arow[j] * (INF*2)  + kb + acol[j]);
            }
            CP_COMMIT();
        }

        uint32_t st = sbase + (it % YNSTG) * YSTGB;
        uint32_t Ab = st, Bb = st + YSUB;
#pragma unroll
        for (int ks = 0; ks < 2; ks++) {
            uint32_t koff = ks * 32;
            uint32_t ah[4][4], bh[2][4];
#pragma unroll
            for (int m = 0; m < 4; m++) {
                uint32_t ra = (uint32_t)(warpM*64 + m*16 + (lane & 15)) * YLDSB + (lane >> 4) * 16 + koff;
                ldsm_x4(ah[m], Ab + ra);
            }
#pragma unroll
            for (int np = 0; np < 2; np++) {
                uint32_t rb = (uint32_t)(warpN*32 + np*16 + (lane & 7) + ((lane >> 4) << 3)) * YLDSB
                            + ((lane >> 3) & 1) * 16 + koff;
                ldsm_x4(bh[np], Bb + rb);
            }
#pragma unroll
            for (int m = 0; m < 4; m++)
#pragma unroll
                for (int np = 0; np < 2; np++) {
                    mma16816h(acc[m][2*np],   ah[m], &bh[np][0]);
                    mma16816h(acc[m][2*np+1], ah[m], &bh[np][2]);
                }
        }
    }

#pragma unroll
    for (int n = 0; n < 4; n++) {
        int col = warpN*32 + n*8 + (lane & 3) * 2;
#pragma unroll
        for (int m = 0; m < 4; m++) {
            int r0 = t0 + warpM*64 + m*16 + (lane >> 2);
            *(float2*)(g_Y + (size_t)r0 * R2 + col) = make_float2(acc[m][n][0], acc[m][n][1]);
            *(float2*)(g_Y + (size_t)(r0 + 8) * R2 + col) = make_float2(acc[m][n][2], acc[m][n][3]);
        }
    }
}

// ---------------- 9. U = Y @ K_b, write fp16 straight into g_Ah columns [1024:1152) ----------------
__global__ void __launch_bounds__(256) u_kernel() {
    __shared__ float As[KT][MT + 4];
    __shared__ float Bs[KT][NT + 4];
    int t0 = blockIdx.x * MT;
    int b = t0 >> 9;
    const float* Kb = g_K + (size_t)b * R2 * R2;
    int tid = threadIdx.x, tx = tid & 15, ty = tid >> 4;
    float acc[8][8];
#pragma unroll
    for (int i = 0; i < 8; i++)
#pragma unroll
        for (int j = 0; j < 8; j++) acc[i][j] = 0.f;
    int lrow = tid >> 1, lcol = (tid & 1) * 16;
    int brow = tid >> 3, bcol = (tid & 7) * 16;
    for (int k0 = 0; k0 < R2; k0 += KT) {
        const float4* ap = (const float4*)(g_Y + (size_t)(t0 + lrow) * R2 + k0 + lcol);
        float4 a0 = ap[0], a1 = ap[1], a2 = ap[2], a3 = ap[3];
        const float4* bp = (const float4*)(Kb + (size_t)(k0 + brow) * R2 + bcol);
        float4 b0 = bp[0], b1 = bp[1], b2 = bp[2], b3 = bp[3];
        __syncthreads();
        As[lcol+ 0][lrow]=a0.x; As[lcol+ 1][lrow]=a0.y; As[lcol+ 2][lrow]=a0.z; As[lcol+ 3][lrow]=a0.w;
        As[lcol+ 4][lrow]=a1.x; As[lcol+ 5][lrow]=a1.y; As[lcol+ 6][lrow]=a1.z; As[lcol+ 7][lrow]=a1.w;
        As[lcol+ 8][lrow]=a2.x; As[lcol+ 9][lrow]=a2.y; As[lcol+10][lrow]=a2.z; As[lcol+11][lrow]=a2.w;
        As[lcol+12][lrow]=a3.x; As[lcol+13][lrow]=a3.y; As[lcol+14][lrow]=a3.z; As[lcol+15][lrow]=a3.w;
        *(float4*)&Bs[brow][bcol+ 0] = b0;
        *(float4*)&Bs[brow][bcol+ 4] = b1;
        *(float4*)&Bs[brow][bcol+ 8] = b2;
        *(float4*)&Bs[brow][bcol+12] = b3;
        __syncthreads();
#pragma unroll 8
        for (int kk = 0; kk < KT; kk++) {
            float4 av0 = *(const float4*)&As[kk][ty*8];
            float4 av1 = *(const float4*)&As[kk][ty*8+4];
            float4 bv0 = *(const float4*)&Bs[kk][tx*8];
            float4 bv1 = *(const float4*)&Bs[kk][tx*8+4];
            float av[8] = {av0.x,av0.y,av0.z,av0.w,av1.x,av1.y,av1.z,av1.w};
            float bv[8] = {bv0.x,bv0.y,bv0.z,bv0.w,bv1.x,bv1.y,bv1.z,bv1.w};
#pragma unroll
            for (int i = 0; i < 8; i++)
#pragma unroll
                for (int j = 0; j < 8; j++) acc[i][j] += av[i] * bv[j];
        }
    }
#pragma unroll
    for (int i = 0; i < 8; i++) {
        __half* dst = g_Ah + (size_t)(t0 + ty*8 + i) * KTOT + INF + tx*8;
#pragma unroll
        for (int j = 0; j < 8; j += 2)
            *(__half2*)(dst + j) = __floats2half2_rn(acc[i][j], acc[i][j+1]);
    }
}

// ---------------- 11a. conv x -> fp16 A columns ----------------
__global__ void convAx_kernel(const float* __restrict__ x) {
    size_t stride = (size_t)gridDim.x * 256;
    const size_t total4 = (size_t)TOK * INF / 4;
    for (size_t i4 = (size_t)blockIdx.x * 256 + threadIdx.x; i4 < total4; i4 += stride) {
        float4 v = ((const float4*)x)[i4];
        size_t idx = i4 * 4;
        size_t t = idx >> 10;
        size_t d = idx & 1023;
        __half2* dst = (__half2*)(g_Ah + t * KTOT + d);
        dst[0] = __floats2half2_rn(v.x, v.y);
        dst[1] = __floats2half2_rn(v.z, v.w);
    }
}

// ---------------- 11b. fused: convB (with inline gt reduction) + scale ----------------
__global__ void convB_fused_kernel(const float* __restrict__ W, const float* __restrict__ sb) {
    int bid = blockIdx.x;
    if (bid < OUTF) {
        int hrow = bid;
        int d = threadIdx.x * 4;    // 288 threads -> d in [0, 1152)
        float4 v;
        if (d < INF) {
            v = *(const float4*)(W + (size_t)hrow * INF + d);
        } else {
            int j = d - INF;
            v = make_float4(0.f, 0.f, 0.f, 0.f);
#pragma unroll
            for (int s = 0; s < 8; s++) {
                float4 p = *(const float4*)(g_Gtp + (size_t)s * OUTF * R2 + (size_t)hrow * R2 + j);
                v.x += p.x; v.y += p.y; v.z += p.z; v.w += p.w;
            }
        }
        __half2* dst = (__half2*)(g_Bh + (size_t)hrow * KTOT + d);
        dst[0] = __floats2half2_rn(v.x, v.y);
        dst[1] = __floats2half2_rn(v.z, v.w);
    } else {
        int idx = (bid - OUTF) * 288 + threadIdx.x;   // scale: BB*OUTF elems
        if (idx < BB * OUTF) {
            int b = idx >> 12, h = idx & 4095;
            float a = 0.f;
#pragma unroll
            for (int k = 0; k < 8; k++) a += g_scoeff[b*8 + k] * sb[k*OUTF + h];
            g_scale[idx] = 1.f + g_scalegate[b] * tanhf(a);
        }
    }
}

// ---------------- 12. main GEMM: fp16 HMMA, 128x256 tile, BK=64, 4 stages ----------------
#define BK      64
#define NCHUNK  (KTOT / BK)   // 18
#define NSTG    4
#define LDSB    144           // bytes per padded smem row (64 fp16 + 16 pad)
#define SUBA    (128 * LDSB)  // 18432 B
#define SUBB    (256 * LDSB)  // 36864 B
#define STGB    (SUBA + SUBB) // 55296 B per stage -> 4 stages = 221184 B

__global__ void __launch_bounds__(256, 1) main_hmma_kernel(const float* __restrict__ bias,
                                                           float* __restrict__ out) {
    extern __shared__ char smemraw[];
    uint32_t sbase = smem_u32(smemraw);
    int tid = threadIdx.x;
    int wid = tid >> 5, lane = tid & 31;
    int h0 = blockIdx.x * 256;
    int t0 = blockIdx.y * 128;
    int warpM = wid >> 2;        // 0..1  (64 rows each)
    int warpN = wid & 3;         // 0..3  (64 cols each)

    const char* gA = (const char*)g_Ah + (size_t)t0 * (KTOT * 2);
    const char* gB = (const char*)g_Bh + (size_t)h0 * (KTOT * 2);

    float acc[4][8][4];
#pragma unroll
    for (int m = 0; m < 4; m++)
#pragma unroll
        for (int n = 0; n < 8; n++)
#pragma unroll
            for (int r = 0; r < 4; r++) acc[m][n][r] = 0.f;

#pragma unroll
    for (int pre = 0; pre < NSTG - 1; pre++) {
        uint32_t st = sbase + pre * STGB;
        size_t kb = (size_t)pre * (BK * 2);
#pragma unroll
        for (int j = 0; j < 4; j++) {
            int c = tid + j * 256;
            int row = c >> 3, col = (c & 7) * 16;
            CP_ASYNC16(st + (uint32_t)row * LDSB + col, gA + (size_t)row * (KTOT*2) + kb + col);
        }
#pragma unroll
        for (int j = 0; j < 8; j++) {
            int c = tid + j * 256;
            int row = c >> 3, col = (c & 7) * 16;
            CP_ASYNC16(st + SUBA + (uint32_t)row * LDSB + col, gB + (size_t)row * (KTOT*2) + kb + col);
        }
        CP_COMMIT();
    }

    for (int it = 0; it < NCHUNK; it++) {
        int rem = NCHUNK - 1 - it;
        if (rem >= 2) { CP_WAIT(2); } else if (rem == 1) { CP_WAIT(1); } else { CP_WAIT(0); }
        __syncthreads();

        if (it + NSTG - 1 < NCHUNK) {
            int nxt = it + NSTG - 1;
            uint32_t st = sbase + (nxt % NSTG) * STGB;
            size_t kb = (size_t)nxt * (BK * 2);
#pragma unroll
            for (int j = 0; j < 4; j++) {
                int c = tid + j * 256;
                int row = c >> 3, col = (c & 7) * 16;
                CP_ASYNC16(st + (uint32_t)row * LDSB + col, gA + (size_t)row * (KTOT*2) + kb + col);
            }
#pragma unroll
            for (int j = 0; j < 8; j++) {
                int c = tid + j * 256;
                int row = c >> 3, col = (c & 7) * 16;
                CP_ASYNC16(st + SUBA + (uint32_t)row * LDSB + col, gB + (size_t)row * (KTOT*2) + kb + col);
            }
            CP_COMMIT();
        }

        uint32_t st = sbase + (it % NSTG) * STGB;
        uint32_t Ahb = st, Bhb = st + SUBA;
#pragma unroll
        for (int ks = 0; ks < 4; ks++) {
            uint32_t koff = ks * 32;   // 16 fp16 = 32 bytes
            uint32_t ah[4][4], bh[4][4];
#pragma unroll
            for (int m = 0; m < 4; m++) {
                uint32_t ra = (uint32_t)(warpM*64 + m*16 + (lane & 15)) * LDSB + (lane >> 4) * 16 + koff;
                ldsm_x4(ah[m], Ahb + ra);
            }
#pragma unroll
            for (int np = 0; np < 4; np++) {
                uint32_t rb = (uint32_t)(warpN*64 + np*16 + (lane & 7) + ((lane >> 4) << 3)) * LDSB
                            + ((lane >> 3) & 1) * 16 + koff;
                ldsm_x4(bh[np], Bhb + rb);
            }
#pragma unroll
            for (int m = 0; m < 4; m++)
#pragma unroll
                for (int np = 0; np < 4; np++) {
                    mma16816h(acc[m][2*np],   ah[m], &bh[np][0]);
                    mma16816h(acc[m][2*np+1], ah[m], &bh[np][2]);
                }
        }
    }

    // epilogue: + bias, * scale, store fp32
    int b = t0 >> 9;
    const float* scp = g_scale + (size_t)b * OUTF;
#pragma unroll
    for (int n = 0; n < 8; n++) {
        int col = h0 + warpN*64 + n*8 + (lane & 3) * 2;
        float s0 = scp[col], s1 = scp[col + 1];
        float bi0 = bias[col], bi1 = bias[col + 1];
#pragma unroll
        for (int m = 0; m < 4; m++) {
            int r0 = t0 + warpM*64 + m*16 + (lane >> 2);
            float2 v0, v1;
            v0.x = (acc[m][n][0] + bi0) * s0;
            v0.y = (acc[m][n][1] + bi1) * s1;
            v1.x = (acc[m][n][2] + bi0) * s0;
            v1.y = (acc[m][n][3] + bi1) * s1;
            *(float2*)(out + (size_t)r0 * OUTF + col) = v0;
            *(float2*)(out + (size_t)(r0 + 8) * OUTF + col) = v1;
        }
    }
}

// ---------------- launcher ----------------
extern "C" void kernel_launch(void* const* d_in, const int* in_sizes, int n_in,
                              void* d_out, int out_size) {
    const float* x    = (const float*)d_in[0];
    const float* W    = (const float*)d_in[1];
    const float* bias = (const float*)d_in[2];
    const float* lb   = (const float*)d_in[3];
    const float* rb   = (const float*)d_in[4];
    const float* sb   = (const float*)d_in[5];
    const float* w1   = (const float*)d_in[6];
    const float* b1   = (const float*)d_in[7];
    const float* rcw  = (const float*)d_in[8];
    const float* rcb  = (const float*)d_in[9];
    const float* rgw  = (const float*)d_in[10];
    const float* rgb  = (const float*)d_in[11];
    const float* scw  = (const float*)d_in[12];
    const float* scb  = (const float*)d_in[13];
    const float* sgw  = (const float*)d_in[14];
    const float* sgb  = (const float*)d_in[15];
    float* out = (float*)d_out;

    cudaFuncSetAttribute(minv_kernel, cudaFuncAttributeMaxDynamicSharedMemorySize, R2 * R2 * 4);
    cudaFuncSetAttribute(main_hmma_kernel, cudaFuncAttributeMaxDynamicSharedMemorySize, NSTG * STGB);
    cudaFuncSetAttribute(y_hmma_kernel, cudaFuncAttributeMaxDynamicSharedMemorySize, YNSTG * YSTGB);

    prep_kernel<<<640, 256>>>(x, lb, rb);
    g0_kernel<<<R2, R2>>>();
    ctrl_kernel<<<BB, HID>>>(w1, b1, rcw, rcb, rgw, rgb, scw, scb, sgw, sgb);
    minv_kernel<<<BB, 1024, R2 * R2 * 4>>>();
    gtp_kernel<<<dim3(OUTF / MT, 8), 256>>>(W);
    convAx_kernel<<<2048, 256>>>(x);
    y_hmma_kernel<<<dim3(1, TOK / 128), 256, YNSTG * YSTGB>>>();
    u_kernel<<<TOK / MT, 256>>>();
    convB_fused_kernel<<<OUTF + 512, 288>>>(W, sb);
    main_hmma_kernel<<<dim3(OUTF / 256, TOK / 128), 256, NSTG * STGB>>>(bias, out);
}

// round 17
// speedup vs baseline: 1.0535x; 1.0535x over previous
#include <cuda_runtime.h>
#include <cuda_bf16.h>
#include <cuda_fp16.h>
#include <math.h>
#include <stdint.h>

#define BB   32
#define NN   512
#define INF  1024
#define OUTF 4096
#define HID  128
#define R2   128           // Woodbury dimension = 2*K_ROT*RANK
#define TOK  (BB*NN)       // 16384
#define CTRL (3*INF)       // 3072
#define KTOT 1152          // INF + R2

#define MT 128
#define NT 128
#define KT 32

// ---------------- device scratch (no allocations allowed) ----------------
__device__ float g_z[BB*CTRL];
__device__ float g_svec[BB*R2];
__device__ float g_rotgate[BB];
__device__ float g_scalegate[BB];
__device__ float g_scoeff[BB*8];
__device__ float g_P[INF*R2];          // [d][i]
__device__ float g_Q[INF*R2];          // [d][i]
__device__ float g_G0[R2*R2];          // Q0^T P
__device__ float g_K[BB*R2*R2];        // per-batch g * Minv * S
__device__ float g_Gtp[8*OUTF*R2];     // split-K partials for G
__device__ float g_Y[(size_t)TOK*R2];  // x @ P
__device__ float g_scale[BB*OUTF];

// fp16 operands: A = [x | U], B = [W | Gt], Pt = P^T (for Y HMMA)
__device__ __align__(256) __half g_Ah[(size_t)TOK*KTOT];
__device__ __align__(256) __half g_Bh[(size_t)OUTF*KTOT];
__device__ __align__(256) __half g_Pth[(size_t)R2*INF];   // [i][d]

// =====================  PTX helpers (plain compute_103-safe)  =====================
__device__ __forceinline__ uint32_t smem_u32(const void* p) {
    uint32_t a;
    asm("{ .reg .u64 t; cvta.to.shared.u64 t, %1; cvt.u32.u64 %0, t; }" : "=r"(a) : "l"(p));
    return a;
}
#define CP_ASYNC16(sa, gp) asm volatile("cp.async.cg.shared.global [%0], [%1], 16;" :: "r"(sa), "l"(gp) : "memory")
#define CP_COMMIT()        asm volatile("cp.async.commit_group;" ::: "memory")
#define CP_WAIT(n)         asm volatile("cp.async.wait_group %0;" :: "n"(n) : "memory")

__device__ __forceinline__ void ldsm_x4(uint32_t* r, uint32_t addr) {
    asm volatile("ldmatrix.sync.aligned.m8n8.x4.shared.b16 {%0,%1,%2,%3}, [%4];"
        : "=r"(r[0]), "=r"(r[1]), "=r"(r[2]), "=r"(r[3]) : "r"(addr));
}
__device__ __forceinline__ void mma16816h(float* c, const uint32_t* a, const uint32_t* b) {
    asm volatile("mma.sync.aligned.m16n8k16.row.col.f32.f16.f16.f32 "
        "{%0,%1,%2,%3}, {%4,%5,%6,%7}, {%8,%9}, {%0,%1,%2,%3};"
        : "+f"(c[0]), "+f"(c[1]), "+f"(c[2]), "+f"(c[3])
        : "r"(a[0]), "r"(a[1]), "r"(a[2]), "r"(a[3]), "r"(b[0]), "r"(b[1]));
}

// ---------------- 1. fused prep: pack (blocks 0..511) + stats (blocks 512..639) ----------------
__global__ void prep_kernel(const float* __restrict__ x,
                            const float* __restrict__ lb, const float* __restrict__ rb) {
    int bid = blockIdx.x;
    if (bid < 512) {
        int idx = bid * 256 + threadIdx.x;     // 0..131071 = INF*R2
        int d = idx >> 7;
        int i = idx & 127;
        int hi = i >> 6;
        int k = (i & 63) >> 3;
        int r = i & 7;
        size_t off = ((size_t)k * INF + d) * 8 + r;
        float L = lb[off], R = rb[off];
        float pv = hi ? R : L;
        g_P[d*R2 + i] = pv;
        g_Q[d*R2 + i] = hi ? -L : R;
        g_Pth[(size_t)i * INF + d] = __float2half_rn(pv);
    } else {
        int ib = bid - 512;                    // 0..127
        int b = ib >> 2;
        int f = (ib & 3) * 256 + threadIdx.x;
        const float* xp = x + (size_t)b * NN * INF + f;
        float cls = xp[0];
        float s = 0.f, s2 = 0.f;
#pragma unroll 8
        for (int n = 0; n < NN; n++) {
            float v = xp[(size_t)n * INF];
            s += v; s2 += v * v;
        }
        float mean = s * (1.0f / NN);
        float var  = s2 * (1.0f / NN) - mean * mean;
        g_z[b*CTRL + f]         = cls;
        g_z[b*CTRL + INF + f]   = mean;
        g_z[b*CTRL + 2*INF + f] = var;
    }
}

// ---------------- 3. G0 = Q0^T P (128x128, K=1024) ----------------
__global__ void g0_kernel() {
    int i = blockIdx.x;
    int j = threadIdx.x;
    float acc = 0.f;
#pragma unroll 8
    for (int d = 0; d < INF; d++)
        acc += g_Q[d*R2 + i] * g_P[d*R2 + j];
    g_G0[i*R2 + j] = acc;
}

// ---------------- 5. controller MLP + norms (inline) + coeffs + gates + svec ----------------
__global__ void ctrl_kernel(const float* __restrict__ w1, const float* __restrict__ b1,
                            const float* __restrict__ rcw, const float* __restrict__ rcb,
                            const float* __restrict__ rgw, const float* __restrict__ rgb,
                            const float* __restrict__ scw, const float* __restrict__ scb,
                            const float* __restrict__ sgw, const float* __restrict__ sgb) {
    __shared__ float zsh[CTRL];
    __shared__ float hsh[HID];
    __shared__ float rcsh[8];
    __shared__ float nsh[8];
    int b = blockIdx.x, t = threadIdx.x;
    for (int j = t; j < CTRL; j += HID) zsh[j] = g_z[b*CTRL + j];
    if (t < 8) {
        int k = t;
        float t1 = 0.f, t2 = 0.f;
        for (int r = 0; r < 8; r++)
            for (int s = 0; s < 8; s++) {
                float LtL = -g_G0[(64 + 8*k + r)*R2 + 8*k + s];
                float RtR =  g_G0[(8*k + r)*R2 + 64 + 8*k + s];
                float RtL_rs = g_G0[(8*k + r)*R2 + 8*k + s];
                float RtL_sr = g_G0[(8*k + s)*R2 + 8*k + r];
                t1 += LtL * RtR;
                t2 += RtL_rs * RtL_sr;
            }
        float n2 = 2.f * (t1 - t2);
        nsh[k] = fmaxf(sqrtf(fmaxf(n2, 0.f)), 1e-6f);
    }
    __syncthreads();
    float acc = b1[t];
    const float* wr = w1 + (size_t)t * CTRL;
    for (int j = 0; j < CTRL; j++) acc += zsh[j] * wr[j];
    float u = 0.7978845608028654f * (acc + 0.044715f * acc * acc * acc);
    hsh[t] = 0.5f * acc * (1.f + tanhf(u));
    __syncthreads();
    if (t < 8) {
        float a = rcb[t];
        const float* w = rcw + t * HID;
        for (int j = 0; j < HID; j++) a += hsh[j] * w[j];
        rcsh[t] = a;
    } else if (t < 16) {
        int k = t - 8;
        float a = scb[k];
        const float* w = scw + k * HID;
        for (int j = 0; j < HID; j++) a += hsh[j] * w[j];
        g_scoeff[b*8 + k] = a;
    } else if (t == 16) {
        float a = rgb[0];
        for (int j = 0; j < HID; j++) a += hsh[j] * rgw[j];
        a += -4.0f;
        g_rotgate[b] = 1.f / (1.f + expf(-a));
    } else if (t == 17) {
        float a = sgb[0];
        for (int j = 0; j < HID; j++) a += hsh[j] * sgw[j];
        a += -2.5f;
        g_scalegate[b] = 1.f / (1.f + expf(-a));
    }
    __syncthreads();
    int k = (t & 63) >> 3;
    g_svec[b*R2 + t] = rcsh[k] / nsh[k];
}

// ---------------- 6. register-resident Gauss-Jordan inverse, K = g*Minv*S ----------------
// Thread (grp, tcol) owns M[grp*16 .. grp*16+15][tcol] in registers.
// Per iteration: pivot column (colv) + pivot row (prow) pass through
// double-buffered smem; ONE barrier per iteration.
__global__ void __launch_bounds__(1024) minv_kernel() {
    __shared__ float colv[2][R2];
    __shared__ float prow[2][R2];
    __shared__ float ssh[R2];
    int b = blockIdx.x;
    int tid = threadIdx.x;
    int tcol = tid & 127;
    int grp = tid >> 7;   // 0..7, rows [grp*16, grp*16+16)
    if (tid < R2) ssh[tid] = g_svec[b*R2 + tid];
    __syncthreads();
    float m[16];
#pragma unroll
    for (int r = 0; r < 16; r++) {
        int i = grp * 16 + r;
        float v = -0.5f * ssh[i] * g_G0[i*R2 + tcol];
        if (i == tcol) v += 1.f;
        m[r] = v;
    }
    for (int k = 0; k < R2; k++) {
        int buf = k & 1;
        if (tcol == k) {
#pragma unroll
            for (int r = 0; r < 16; r++) colv[buf][grp*16 + r] = m[r];
        }
        if (grp == (k >> 4)) prow[buf][tcol] = m[k & 15];
        __syncthreads();
        float invp = 1.f / prow[buf][k];
        float rk = (tcol == k ? 1.f : prow[buf][tcol]) * invp;
        int kg = k >> 4, kr = k & 15;
        bool myrowk = (grp == kg);
        float zv = (tcol == k) ? 0.f : 1.f;   // multiplier to zero pivot column
#pragma unroll
        for (int r = 0; r < 16; r++) {
            if (myrowk && r == kr) {
                m[r] = rk;
            } else {
                m[r] = m[r] * zv - colv[buf][grp*16 + r] * rk;
            }
        }
        // no second barrier: next iteration uses the other buffer
    }
    __syncthreads();
    float g = g_rotgate[b];
#pragma unroll
    for (int r = 0; r < 16; r++) {
        int i = grp * 16 + r;
        g_K[(size_t)b*R2*R2 + i*R2 + tcol] = g * m[r] * ssh[tcol];
    }
}

// ---------------- 7. G partials (split-K) ----------------
__global__ void __launch_bounds__(256) gtp_kernel(const float* __restrict__ W) {
    __shared__ float As[KT][MT + 4];
    __shared__ float Bs[KT][NT + 4];
    int h0 = blockIdx.x * MT;
    int s = blockIdx.y;
    int d0 = s * 128;
    int tid = threadIdx.x, tx = tid & 15, ty = tid >> 4;
    float acc[8][8];
#pragma unroll
    for (int i = 0; i < 8; i++)
#pragma unroll
        for (int j = 0; j < 8; j++) acc[i][j] = 0.f;
    int lrow = tid >> 1, lcol = (tid & 1) * 16;
    int brow = tid >> 3, bcol = (tid & 7) * 16;
    for (int k0 = 0; k0 < 128; k0 += KT) {
        const float4* ap = (const float4*)(W + (size_t)(h0 + lrow) * INF + d0 + k0 + lcol);
        float4 a0 = ap[0], a1 = ap[1], a2 = ap[2], a3 = ap[3];
        const float4* bp = (const float4*)(g_Q + (size_t)(d0 + k0 + brow) * R2 + bcol);
        float4 b0 = bp[0], b1 = bp[1], b2 = bp[2], b3 = bp[3];
        __syncthreads();
        As[lcol+ 0][lrow]=a0.x; As[lcol+ 1][lrow]=a0.y; As[lcol+ 2][lrow]=a0.z; As[lcol+ 3][lrow]=a0.w;
        As[lcol+ 4][lrow]=a1.x; As[lcol+ 5][lrow]=a1.y; As[lcol+ 6][lrow]=a1.z; As[lcol+ 7][lrow]=a1.w;
        As[lcol+ 8][lrow]=a2.x; As[lcol+ 9][lrow]=a2.y; As[lcol+10][lrow]=a2.z; As[lcol+11][lrow]=a2.w;
        As[lcol+12][lrow]=a3.x; As[lcol+13][lrow]=a3.y; As[lcol+14][lrow]=a3.z; As[lcol+15][lrow]=a3.w;
        *(float4*)&Bs[brow][bcol+ 0] = b0;
        *(float4*)&Bs[brow][bcol+ 4] = b1;
        *(float4*)&Bs[brow][bcol+ 8] = b2;
        *(float4*)&Bs[brow][bcol+12] = b3;
        __syncthreads();
#pragma unroll 8
        for (int kk = 0; kk < KT; kk++) {
            float4 av0 = *(const float4*)&As[kk][ty*8];
            float4 av1 = *(const float4*)&As[kk][ty*8+4];
            float4 bv0 = *(const float4*)&Bs[kk][tx*8];
            float4 bv1 = *(const float4*)&Bs[kk][tx*8+4];
            float av[8] = {av0.x,av0.y,av0.z,av0.w,av1.x,av1.y,av1.z,av1.w};
            float bv[8] = {bv0.x,bv0.y,bv0.z,bv0.w,bv1.x,bv1.y,bv1.z,bv1.w};
#pragma unroll
            for (int i = 0; i < 8; i++)
#pragma unroll
                for (int j = 0; j < 8; j++) acc[i][j] += av[i] * bv[j];
        }
    }
#pragma unroll
    for (int i = 0; i < 8; i++)
#pragma unroll
        for (int j = 0; j < 8; j++)
            g_Gtp[((size_t)s * OUTF + h0 + ty*8 + i) * R2 + tx*8 + j] = acc[i][j];
}

// ---------------- 8. Y = x @ P via fp16 HMMA ----------------
#define YBK     32
#define YNCHUNK (INF / YBK)   // 32
#define YNSTG   3
#define YLDSB   80
#define YSUB    (128 * YLDSB)       // 10240
#define YSTGB   (2 * YSUB)          // 20480

__global__ void __launch_bounds__(256, 1) y_hmma_kernel() {
    extern __shared__ char smemraw[];
    uint32_t sbase = smem_u32(smemraw);
    int tid = threadIdx.x;
    int wid = tid >> 5, lane = tid & 31;
    int t0 = blockIdx.y * 128;
    int warpM = wid >> 2;        // 0..1 (64 rows)
    int warpN = wid & 3;         // 0..3 (32 cols)

    const char* gA = (const char*)g_Ah + (size_t)t0 * (KTOT * 2);
    const char* gB = (const char*)g_Pth;

    float acc[4][4][4];
#pragma unroll
    for (int m = 0; m < 4; m++)
#pragma unroll
        for (int n = 0; n < 4; n++)
#pragma unroll
            for (int r = 0; r < 4; r++) acc[m][n][r] = 0.f;

    int arow[2], acol[2];
#pragma unroll
    for (int j = 0; j < 2; j++) { int c = j*256 + tid; arow[j] = c >> 2; acol[j] = (c & 3) * 16; }

#pragma unroll
    for (int pre = 0; pre < YNSTG - 1; pre++) {
        uint32_t st = sbase + pre * YSTGB;
        size_t kb = (size_t)pre * (YBK * 2);
#pragma unroll
        for (int j = 0; j < 2; j++) {
            CP_ASYNC16(st + (uint32_t)arow[j] * YLDSB + acol[j],          gA + (size_t)arow[j] * (KTOT*2) + kb + acol[j]);
            CP_ASYNC16(st + YSUB + (uint32_t)arow[j] * YLDSB + acol[j],   gB + (size_t)arow[j] * (INF*2)  + kb + acol[j]);
        }
        CP_COMMIT();
    }

    for (int it = 0; it < YNCHUNK; it++) {
        if (it < YNCHUNK - 1) { CP_WAIT(1); } else { CP_WAIT(0); }
        __syncthreads();

        if (it + YNSTG - 1 < YNCHUNK) {
            int nxt = it + YNSTG - 1;
            uint32_t st = sbase + (nxt % YNSTG) * YSTGB;
            size_t kb = (size_t)nxt * (YBK * 2);
#pragma unroll
            for (int j = 0; j < 2; j++) {
                CP_ASYNC16(st + (uint32_t)arow[j] * YLDSB + acol[j],        gA + (size_t)arow[j] * (KTOT*2) + kb + acol[j]);
                CP_ASYNC16(st + YSUB + (uint32_t)arow[j] * YLDSB + acol[j], gB + (size_t)arow[j] * (INF*2)  + kb + acol[j]);
            }
            CP_COMMIT();
        }

        uint32_t st = sbase + (it % YNSTG) * YSTGB;
        uint32_t Ab = st, Bb = st + YSUB;
#pragma unroll
        for (int ks = 0; ks < 2; ks++) {
            uint32_t koff = ks * 32;
            uint32_t ah[4][4], bh[2][4];
#pragma unroll
            for (int m = 0; m < 4; m++) {
                uint32_t ra = (uint32_t)(warpM*64 + m*16 + (lane & 15)) * YLDSB + (lane >> 4) * 16 + koff;
                ldsm_x4(ah[m], Ab + ra);
            }
#pragma unroll
            for (int np = 0; np < 2; np++) {
                uint32_t rb = (uint32_t)(warpN*32 + np*16 + (lane & 7) + ((lane >> 4) << 3)) * YLDSB
                            + ((lane >> 3) & 1) * 16 + koff;
                ldsm_x4(bh[np], Bb + rb);
            }
#pragma unroll
            for (int m = 0; m < 4; m++)
#pragma unroll
                for (int np = 0; np < 2; np++) {
                    mma16816h(acc[m][2*np],   ah[m], &bh[np][0]);
                    mma16816h(acc[m][2*np+1], ah[m], &bh[np][2]);
                }
        }
    }

#pragma unroll
    for (int n = 0; n < 4; n++) {
        int col = warpN*32 + n*8 + (lane & 3) * 2;
#pragma unroll
        for (int m = 0; m < 4; m++) {
            int r0 = t0 + warpM*64 + m*16 + (lane >> 2);
            *(float2*)(g_Y + (size_t)r0 * R2 + col) = make_float2(acc[m][n][0], acc[m][n][1]);
            *(float2*)(g_Y + (size_t)(r0 + 8) * R2 + col) = make_float2(acc[m][n][2], acc[m][n][3]);
        }
    }
}

// ---------------- 9. U = Y @ K_b, write fp16 straight into g_Ah columns [1024:1152) ----------------
__global__ void __launch_bounds__(256) u_kernel() {
    __shared__ float As[KT][MT + 4];
    __shared__ float Bs[KT][NT + 4];
    int t0 = blockIdx.x * MT;
    int b = t0 >> 9;
    const float* Kb = g_K + (size_t)b * R2 * R2;
    int tid = threadIdx.x, tx = tid & 15, ty = tid >> 4;
    float acc[8][8];
#pragma unroll
    for (int i = 0; i < 8; i++)
#pragma unroll
        for (int j = 0; j < 8; j++) acc[i][j] = 0.f;
    int lrow = tid >> 1, lcol = (tid & 1) * 16;
    int brow = tid >> 3, bcol = (tid & 7) * 16;
    for (int k0 = 0; k0 < R2; k0 += KT) {
        const float4* ap = (const float4*)(g_Y + (size_t)(t0 + lrow) * R2 + k0 + lcol);
        float4 a0 = ap[0], a1 = ap[1], a2 = ap[2], a3 = ap[3];
        const float4* bp = (const float4*)(Kb + (size_t)(k0 + brow) * R2 + bcol);
        float4 b0 = bp[0], b1 = bp[1], b2 = bp[2], b3 = bp[3];
        __syncthreads();
        As[lcol+ 0][lrow]=a0.x; As[lcol+ 1][lrow]=a0.y; As[lcol+ 2][lrow]=a0.z; As[lcol+ 3][lrow]=a0.w;
        As[lcol+ 4][lrow]=a1.x; As[lcol+ 5][lrow]=a1.y; As[lcol+ 6][lrow]=a1.z; As[lcol+ 7][lrow]=a1.w;
        As[lcol+ 8][lrow]=a2.x; As[lcol+ 9][lrow]=a2.y; As[lcol+10][lrow]=a2.z; As[lcol+11][lrow]=a2.w;
        As[lcol+12][lrow]=a3.x; As[lcol+13][lrow]=a3.y; As[lcol+14][lrow]=a3.z; As[lcol+15][lrow]=a3.w;
        *(float4*)&Bs[brow][bcol+ 0] = b0;
        *(float4*)&Bs[brow][bcol+ 4] = b1;
        *(float4*)&Bs[brow][bcol+ 8] = b2;
        *(float4*)&Bs[brow][bcol+12] = b3;
        __syncthreads();
#pragma unroll 8
        for (int kk = 0; kk < KT; kk++) {
            float4 av0 = *(const float4*)&As[kk][ty*8];
            float4 av1 = *(const float4*)&As[kk][ty*8+4];
            float4 bv0 = *(const float4*)&Bs[kk][tx*8];
            float4 bv1 = *(const float4*)&Bs[kk][tx*8+4];
            float av[8] = {av0.x,av0.y,av0.z,av0.w,av1.x,av1.y,av1.z,av1.w};
            float bv[8] = {bv0.x,bv0.y,bv0.z,bv0.w,bv1.x,bv1.y,bv1.z,bv1.w};
#pragma unroll
            for (int i = 0; i < 8; i++)
#pragma unroll
                for (int j = 0; j < 8; j++) acc[i][j] += av[i] * bv[j];
        }
    }
#pragma unroll
    for (int i = 0; i < 8; i++) {
        __half* dst = g_Ah + (size_t)(t0 + ty*8 + i) * KTOT + INF + tx*8;
#pragma unroll
        for (int j = 0; j < 8; j += 2)
            *(__half2*)(dst + j) = __floats2half2_rn(acc[i][j], acc[i][j+1]);
    }
}

// ---------------- 11a. conv x -> fp16 A columns ----------------
__global__ void convAx_kernel(const float* __restrict__ x) {
    size_t stride = (size_t)gridDim.x * 256;
    const size_t total4 = (size_t)TOK * INF / 4;
    for (size_t i4 = (size_t)blockIdx.x * 256 + threadIdx.x; i4 < total4; i4 += stride) {
        float4 v = ((const float4*)x)[i4];
        size_t idx = i4 * 4;
        size_t t = idx >> 10;
        size_t d = idx & 1023;
        __half2* dst = (__half2*)(g_Ah + t * KTOT + d);
        dst[0] = __floats2half2_rn(v.x, v.y);
        dst[1] = __floats2half2_rn(v.z, v.w);
    }
}

// ---------------- 11b. fused: convB (with inline gt reduction) + scale ----------------
__global__ void convB_fused_kernel(const float* __restrict__ W, const float* __restrict__ sb) {
    int bid = blockIdx.x;
    if (bid < OUTF) {
        int hrow = bid;
        int d = threadIdx.x * 4;    // 288 threads -> d in [0, 1152)
        float4 v;
        if (d < INF) {
            v = *(const float4*)(W + (size_t)hrow * INF + d);
        } else {
            int j = d - INF;
            v = make_float4(0.f, 0.f, 0.f, 0.f);
#pragma unroll
            for (int s = 0; s < 8; s++) {
                float4 p = *(const float4*)(g_Gtp + (size_t)s * OUTF * R2 + (size_t)hrow * R2 + j);
                v.x += p.x; v.y += p.y; v.z += p.z; v.w += p.w;
            }
        }
        __half2* dst = (__half2*)(g_Bh + (size_t)hrow * KTOT + d);
        dst[0] = __floats2half2_rn(v.x, v.y);
        dst[1] = __floats2half2_rn(v.z, v.w);
    } else {
        int idx = (bid - OUTF) * 288 + threadIdx.x;   // scale: BB*OUTF elems
        if (idx < BB * OUTF) {
            int b = idx >> 12, h = idx & 4095;
            float a = 0.f;
#pragma unroll
            for (int k = 0; k < 8; k++) a += g_scoeff[b*8 + k] * sb[k*OUTF + h];
            g_scale[idx] = 1.f + g_scalegate[b] * tanhf(a);
        }
    }
}

// ---------------- 12. main GEMM: fp16 HMMA, 128x256 tile, BK=64, 3 stages ----------------
#define BK      64
#define NCHUNK  (KTOT / BK)   // 18
#define NSTG    3
#define LDSB    144           // bytes per padded smem row (64 fp16 + 16 pad)
#define SUBA    (128 * LDSB)  // 18432 B
#define SUBB    (256 * LDSB)  // 36864 B
#define STGB    (SUBA + SUBB) // 55296 B per stage -> 3 stages = 165888 B

__global__ void __launch_bounds__(256, 1) main_hmma_kernel(const float* __restrict__ bias,
                                                           float* __restrict__ out) {
    extern __shared__ char smemraw[];
    uint32_t sbase = smem_u32(smemraw);
    int tid = threadIdx.x;
    int wid = tid >> 5, lane = tid & 31;
    int h0 = blockIdx.x * 256;
    int t0 = blockIdx.y * 128;
    int warpM = wid >> 2;        // 0..1  (64 rows each)
    int warpN = wid & 3;         // 0..3  (64 cols each)

    const char* gA = (const char*)g_Ah + (size_t)t0 * (KTOT * 2);
    const char* gB = (const char*)g_Bh + (size_t)h0 * (KTOT * 2);

    float acc[4][8][4];
#pragma unroll
    for (int m = 0; m < 4; m++)
#pragma unroll
        for (int n = 0; n < 8; n++)
#pragma unroll
            for (int r = 0; r < 4; r++) acc[m][n][r] = 0.f;

#pragma unroll
    for (int pre = 0; pre < NSTG - 1; pre++) {
        uint32_t st = sbase + pre * STGB;
        size_t kb = (size_t)pre * (BK * 2);
#pragma unroll
        for (int j = 0; j < 4; j++) {
            int c = tid + j * 256;
            int row = c >> 3, col = (c & 7) * 16;
            CP_ASYNC16(st + (uint32_t)row * LDSB + col, gA + (size_t)row * (KTOT*2) + kb + col);
        }
#pragma unroll
        for (int j = 0; j < 8; j++) {
            int c = tid + j * 256;
            int row = c >> 3, col = (c & 7) * 16;
            CP_ASYNC16(st + SUBA + (uint32_t)row * LDSB + col, gB + (size_t)row * (KTOT*2) + kb + col);
        }
        CP_COMMIT();
    }

    for (int it = 0; it < NCHUNK; it++) {
        if (it < NCHUNK - 1) { CP_WAIT(1); } else { CP_WAIT(0); }
        __syncthreads();

        if (it + NSTG - 1 < NCHUNK) {
            int nxt = it + NSTG - 1;
            uint32_t st = sbase + (nxt % NSTG) * STGB;
            size_t kb = (size_t)nxt * (BK * 2);
#pragma unroll
            for (int j = 0; j < 4; j++) {
                int c = tid + j * 256;
                int row = c >> 3, col = (c & 7) * 16;
                CP_ASYNC16(st + (uint32_t)row * LDSB + col, gA + (size_t)row * (KTOT*2) + kb + col);
            }
#pragma unroll
            for (int j = 0; j < 8; j++) {
                int c = tid + j * 256;
                int row = c >> 3, col = (c & 7) * 16;
                CP_ASYNC16(st + SUBA + (uint32_t)row * LDSB + col, gB + (size_t)row * (KTOT*2) + kb + col);
            }
            CP_COMMIT();
        }

        uint32_t st = sbase + (it % NSTG) * STGB;
        uint32_t Ahb = st, Bhb = st + SUBA;
#pragma unroll
        for (int ks = 0; ks < 4; ks++) {
            uint32_t koff = ks * 32;   // 16 fp16 = 32 bytes
            uint32_t ah[4][4], bh[4][4];
#pragma unroll
            for (int m = 0; m < 4; m++) {
                uint32_t ra = (uint32_t)(warpM*64 + m*16 + (lane & 15)) * LDSB + (lane >> 4) * 16 + koff;
                ldsm_x4(ah[m], Ahb + ra);
            }
#pragma unroll
            for (int np = 0; np < 4; np++) {
                uint32_t rb = (uint32_t)(warpN*64 + np*16 + (lane & 7) + ((lane >> 4) << 3)) * LDSB
                            + ((lane >> 3) & 1) * 16 + koff;
                ldsm_x4(bh[np], Bhb + rb);
            }
#pragma unroll
            for (int m = 0; m < 4; m++)
#pragma unroll
                for (int np = 0; np < 4; np++) {
                    mma16816h(acc[m][2*np],   ah[m], &bh[np][0]);
                    mma16816h(acc[m][2*np+1], ah[m], &bh[np][2]);
                }
        }
    }

    // epilogue: + bias, * scale, store fp32
    int b = t0 >> 9;
    const float* scp = g_scale + (size_t)b * OUTF;
#pragma unroll
    for (int n = 0; n < 8; n++) {
        int col = h0 + warpN*64 + n*8 + (lane & 3) * 2;
        float s0 = scp[col], s1 = scp[col + 1];
        float bi0 = bias[col], bi1 = bias[col + 1];
#pragma unroll
        for (int m = 0; m < 4; m++) {
            int r0 = t0 + warpM*64 + m*16 + (lane >> 2);
            float2 v0, v1;
            v0.x = (acc[m][n][0] + bi0) * s0;
            v0.y = (acc[m][n][1] + bi1) * s1;
            v1.x = (acc[m][n][2] + bi0) * s0;
            v1.y = (acc[m][n][3] + bi1) * s1;
            *(float2*)(out + (size_t)r0 * OUTF + col) = v0;
            *(float2*)(out + (size_t)(r0 + 8) * OUTF + col) = v1;
        }
    }
}

// ---------------- launcher ----------------
extern "C" void kernel_launch(void* const* d_in, const int* in_sizes, int n_in,
                              void* d_out, int out_size) {
    const float* x    = (const float*)d_in[0];
    const float* W    = (const float*)d_in[1];
    const float* bias = (const float*)d_in[2];
    const float* lb   = (const float*)d_in[3];
    const float* rb   = (const float*)d_in[4];
    const float* sb   = (const float*)d_in[5];
    const float* w1   = (const float*)d_in[6];
    const float* b1   = (const float*)d_in[7];
    const float* rcw  = (const float*)d_in[8];
    const float* rcb  = (const float*)d_in[9];
    const float* rgw  = (const float*)d_in[10];
    const float* rgb  = (const float*)d_in[11];
    const float* scw  = (const float*)d_in[12];
    const float* scb  = (const float*)d_in[13];
    const float* sgw  = (const float*)d_in[14];
    const float* sgb  = (const float*)d_in[15];
    float* out = (float*)d_out;

    cudaFuncSetAttribute(main_hmma_kernel, cudaFuncAttributeMaxDynamicSharedMemorySize, NSTG * STGB);
    cudaFuncSetAttribute(y_hmma_kernel, cudaFuncAttributeMaxDynamicSharedMemorySize, YNSTG * YSTGB);

    prep_kernel<<<640, 256>>>(x, lb, rb);
    g0_kernel<<<R2, R2>>>();
    ctrl_kernel<<<BB, HID>>>(w1, b1, rcw, rcb, rgw, rgb, scw, scb, sgw, sgb);
    minv_kernel<<<BB, 1024>>>();
    gtp_kernel<<<dim3(OUTF / MT, 8), 256>>>(W);
    convAx_kernel<<<2048, 256>>>(x);
    y_hmma_kernel<<<dim3(1, TOK / 128), 256, YNSTG * YSTGB>>>();
    u_kernel<<<TOK / MT, 256>>>();
    convB_fused_kernel<<<OUTF + 512, 288>>>(W, sb);
    main_hmma_kernel<<<dim3(OUTF / 256, TOK / 128), 256, NSTG * STGB>>>(bias, out);
}